// round 17
// baseline (speedup 1.0000x reference)
#include <cuda_runtime.h>
#include <cuda_bf16.h>
#include <cstdint>
#include <cmath>

// ============================================================================
// Inputs: f32 (bf16-valued, widened by harness). K=2048, R=32768.
// Output mode 0: fp32 concat [q_as_f32 (R*K) | scale (R)].
//
// R16 = 788.5us, fully-accounted floor: mainloop 686 + qwrite 34 + rdv 4 +
// convert 56 + transpose 8 + launches. R17 micro-harvest:
//  1) transpose folded into convert kernel (block-range dispatch, one launch)
//  2) q-tile stores use st.global.cs (streaming; output never re-read)
//  3) GEMM mainloop byte-identical to measured best (R14/R16).
// ============================================================================

__device__ __nv_bfloat16 g_xb[(size_t)67108864];        // 134 MB x as bf16
__device__ __nv_bfloat16 g_ht[(size_t)2048 * 2048];     // 8 MB h^T as bf16
__device__ float        g_y[(size_t)67108864];          // fallback (mode!=0)
__device__ unsigned     g_absmax[32768];                // per-row absmax bits
__device__ unsigned     g_cnt[1024];                    // per-m-slab arrivals

static constexpr int MT = 128, NT = 128, KC = 64, STAGES = 3;
static constexpr int THREADS = 128;
static constexpr int A_STAGE_BYTES = MT * KC * 2;           // 16384
static constexpr int B_STAGE_BYTES = NT * KC * 2;           // 16384
static constexpr int SMEM_B_BASE = STAGES * A_STAGE_BYTES;  // 49152
static constexpr int SMEM_TOTAL = STAGES * (A_STAGE_BYTES + B_STAGE_BYTES); // 98304

__device__ __forceinline__ uint32_t smem_u32(const void* p) {
    uint32_t a;
    asm("{ .reg .u64 t; cvta.to.shared.u64 t, %1; cvt.u32.u64 %0, t; }"
        : "=r"(a) : "l"(p));
    return a;
}
__device__ __forceinline__ uint32_t swz(uint32_t off) {
    return off ^ ((off >> 3) & 0x70u);
}
__device__ __forceinline__ void cp_async16(uint32_t s_addr, const void* g_addr) {
    asm volatile("cp.async.cg.shared.global [%0], [%1], 16;"
                 :: "r"(s_addr), "l"(g_addr) : "memory");
}
#define CP_COMMIT() asm volatile("cp.async.commit_group;" ::: "memory")
#define CP_WAIT(n)  asm volatile("cp.async.wait_group %0;" :: "n"(n) : "memory")

__device__ __forceinline__ void ldmatrix_x4(uint32_t* r, uint32_t addr) {
    asm volatile("ldmatrix.sync.aligned.m8n8.x4.shared.b16 {%0,%1,%2,%3}, [%4];"
                 : "=r"(r[0]), "=r"(r[1]), "=r"(r[2]), "=r"(r[3]) : "r"(addr));
}
__device__ __forceinline__ void mma_16816(float* d, const uint32_t* a,
                                          uint32_t b0, uint32_t b1) {
    asm volatile(
        "mma.sync.aligned.m16n8k16.row.col.f32.bf16.bf16.f32 "
        "{%0,%1,%2,%3}, {%4,%5,%6,%7}, {%8,%9}, {%0,%1,%2,%3};"
        : "+f"(d[0]), "+f"(d[1]), "+f"(d[2]), "+f"(d[3])
        : "r"(a[0]), "r"(a[1]), "r"(a[2]), "r"(a[3]), "r"(b0), "r"(b1));
}
__device__ __forceinline__ void st_cs_f2(float* p, float v0, float v1) {
    asm volatile("st.global.cs.v2.f32 [%0], {%1, %2};"
                 :: "l"(p), "f"(v0), "f"(v1) : "memory");
}

// ============================================================================
// prep kernel: blocks [0, tb) transpose h (f32 -> bf16 h^T tiles);
//              blocks [tb, ...) convert x f32->bf16 + zero meta.
// ============================================================================
__global__ void __launch_bounds__(256) prep_kernel(
    const float4* __restrict__ xf, long long n4,
    const float* __restrict__ h, int K, int R, int tb) {
    __shared__ float tile[32][33];
    if ((int)blockIdx.x < tb) {
        // ---- transpose portion ----
        int tdim = K / 32;                       // 64
        int bx = blockIdx.x % tdim;
        int by = blockIdx.x / tdim;
        int tx = threadIdx.x & 31;
        int ty = threadIdx.x >> 5;               // 0..7
        int x = bx * 32 + tx;
        int y = by * 32 + ty;
#pragma unroll
        for (int j = 0; j < 32; j += 8)
            tile[ty + j][tx] = h[(size_t)(y + j) * K + x];
        __syncthreads();
        int xo = by * 32 + tx;
        int yo = bx * 32 + ty;
#pragma unroll
        for (int j = 0; j < 32; j += 8)
            g_ht[(size_t)(yo + j) * K + xo] =
                __float2bfloat16(tile[tx][ty + j]);
        return;
    }
    // ---- convert portion ----
    long long i = (long long)(blockIdx.x - tb) * blockDim.x + threadIdx.x;
    if (i < R) g_absmax[i] = 0u;
    if (i < 1024) g_cnt[i] = 0u;
    long long base = i * 2;
    if (base + 1 < n4) {
        float4 v0 = xf[base + 0];
        float4 v1 = xf[base + 1];
        __nv_bfloat16 o[8] = {
            __float2bfloat16(v0.x), __float2bfloat16(v0.y),
            __float2bfloat16(v0.z), __float2bfloat16(v0.w),
            __float2bfloat16(v1.x), __float2bfloat16(v1.y),
            __float2bfloat16(v1.z), __float2bfloat16(v1.w)};
        *reinterpret_cast<uint4*>(&g_xb[base * 4]) =
            *reinterpret_cast<const uint4*>(o);
    }
}

// ============================================================================
// GEMM + fused absmax + fused cross-CTA quantization epilogue.
// 4 warps = 2(M) x 2(N), warp tile 64x64, 2 CTAs/SM, 3-stage pipeline.
// (mainloop byte-identical to measured-best R14/R16)
// ============================================================================
__global__ void __launch_bounds__(THREADS, 2) gemm_fused_kernel(
    void* __restrict__ d_out, int K, long long R, int mode) {
    extern __shared__ char smem[];
    const uint32_t smem_base = smem_u32(smem);
    const int tid = threadIdx.x;
    const int wid = tid >> 5;
    const int lane = tid & 31;
    const int wm = wid >> 1;
    const int wn = wid & 1;

    const int m0 = blockIdx.y * MT;
    const int n0 = blockIdx.x * NT;

    const int lrow0 = tid >> 3;
    const int lcol  = tid & 7;
    const uint32_t soff0 = swz((uint32_t)lrow0 * 128u + (uint32_t)lcol * 16u);
    const size_t stride16 = (size_t)16 * K;
    const __nv_bfloat16* Aptr = g_xb + (size_t)(m0 + lrow0) * K + lcol * 8;
    const __nv_bfloat16* Bptr = g_ht + (size_t)(n0 + lrow0) * K + lcol * 8;

    const int lrow = lane & 15;
    const int lkb  = (lane >> 4) * 8;
    uint32_t araw[4], braw[4];
#pragma unroll
    for (int mi = 0; mi < 4; mi++)
        araw[mi] = (uint32_t)(wm * 64 + mi * 16 + lrow) * 128u +
                   (uint32_t)lkb * 2u;
#pragma unroll
    for (int nj = 0; nj < 4; nj++)
        braw[nj] = (uint32_t)(wn * 64 + nj * 16 + lrow) * 128u +
                   (uint32_t)lkb * 2u;

    float d[4][8][4];
#pragma unroll
    for (int mi = 0; mi < 4; mi++)
#pragma unroll
        for (int ni = 0; ni < 8; ni++)
#pragma unroll
            for (int j = 0; j < 4; j++) d[mi][ni][j] = 0.0f;

#pragma unroll
    for (int s = 0; s < STAGES - 1; s++) {
        uint32_t sA = smem_base + s * A_STAGE_BYTES;
        uint32_t sB = smem_base + SMEM_B_BASE + s * B_STAGE_BYTES;
#pragma unroll
        for (int i = 0; i < 8; i++)
            cp_async16(sA + soff0 + i * 2048u, Aptr + s * KC + i * stride16);
#pragma unroll
        for (int i = 0; i < 8; i++)
            cp_async16(sB + soff0 + i * 2048u, Bptr + s * KC + i * stride16);
        CP_COMMIT();
    }

    const int NCHUNK = K / KC;

    for (int kc = 0; kc < NCHUNK; kc++) {
        CP_WAIT(STAGES - 2);
        __syncthreads();

        const bool do_load = (kc + STAGES - 1) < NCHUNK;
        const int wst = (kc + STAGES - 1) % STAGES;
        const uint32_t wA = smem_base + wst * A_STAGE_BYTES;
        const uint32_t wB = smem_base + SMEM_B_BASE + wst * B_STAGE_BYTES;
        const int kb_next = (kc + STAGES - 1) * KC;

        const int st = kc % STAGES;
        const uint32_t sA = smem_base + st * A_STAGE_BYTES;
        const uint32_t sB = smem_base + SMEM_B_BASE + st * B_STAGE_BYTES;

        uint32_t a[2][4][4], b[2][4][4];
#pragma unroll
        for (int mi = 0; mi < 4; mi++)
            ldmatrix_x4(a[0][mi], sA + swz(araw[mi]));
#pragma unroll
        for (int nj = 0; nj < 4; nj++)
            ldmatrix_x4(b[0][nj], sB + swz(braw[nj]));

#pragma unroll
        for (int s = 0; s < KC / 16; s++) {
            const int cur = s & 1;
            const int nxt = cur ^ 1;
            if (s < KC / 16 - 1) {
                uint32_t so = (uint32_t)(s + 1) * 32u;
#pragma unroll
                for (int mi = 0; mi < 4; mi++)
                    ldmatrix_x4(a[nxt][mi], sA + swz(araw[mi] + so));
#pragma unroll
                for (int nj = 0; nj < 4; nj++)
                    ldmatrix_x4(b[nxt][nj], sB + swz(braw[nj] + so));
            }
            if (do_load) {
#pragma unroll
                for (int j = 0; j < 4; j++) {
                    int i = s * 4 + j;
                    uint32_t dst = (i < 8 ? wA : wB) + soff0 + (i & 7) * 2048u;
                    const __nv_bfloat16* src =
                        (i < 8 ? Aptr : Bptr) + kb_next + (i & 7) * stride16;
                    cp_async16(dst, src);
                }
            }
#pragma unroll
            for (int mi = 0; mi < 4; mi++)
#pragma unroll
                for (int nj = 0; nj < 4; nj++) {
                    mma_16816(d[mi][2 * nj + 0], a[cur][mi],
                              b[cur][nj][0], b[cur][nj][2]);
                    mma_16816(d[mi][2 * nj + 1], a[cur][mi],
                              b[cur][nj][1], b[cur][nj][3]);
                }
        }
        CP_COMMIT();
    }

    // ---- epilogue phase 1: row absmax + atomicMax ----
    const int g = lane >> 2;
    const int tc = (lane & 3) * 2;
#pragma unroll
    for (int mi = 0; mi < 4; mi++) {
#pragma unroll
        for (int half = 0; half < 2; half++) {
            int r = m0 + wm * 64 + mi * 16 + half * 8 + g;
            float mx = 0.0f;
#pragma unroll
            for (int ni = 0; ni < 8; ni++)
                mx = fmaxf(mx, fmaxf(fabsf(d[mi][ni][half * 2 + 0]),
                                     fabsf(d[mi][ni][half * 2 + 1])));
            mx = fmaxf(mx, __shfl_xor_sync(0xFFFFFFFFu, mx, 1));
            mx = fmaxf(mx, __shfl_xor_sync(0xFFFFFFFFu, mx, 2));
            if ((lane & 3) == 0)
                atomicMax(&g_absmax[r], __float_as_uint(mx));
        }
    }

    if (mode != 0) {
#pragma unroll
        for (int mi = 0; mi < 4; mi++)
#pragma unroll
            for (int half = 0; half < 2; half++) {
                int r = m0 + wm * 64 + mi * 16 + half * 8 + g;
                float* yrow = g_y + (size_t)r * K + n0 + wn * 64;
#pragma unroll
                for (int ni = 0; ni < 8; ni++)
                    *reinterpret_cast<float2*>(yrow + ni * 8 + tc) =
                        make_float2(d[mi][ni][half * 2 + 0],
                                    d[mi][ni][half * 2 + 1]);
            }
        return;
    }

    // ---- epilogue phase 2: slab rendezvous ----
    __syncthreads();
    if (tid == 0) {
        __threadfence();
        atomicAdd(&g_cnt[blockIdx.y], 1u);
        unsigned target = gridDim.x;
        unsigned v;
        do {
            asm volatile("ld.acquire.gpu.global.u32 %0, [%1];"
                         : "=r"(v) : "l"(&g_cnt[blockIdx.y]));
        } while (v < target);
    }
    __syncthreads();

    // ---- epilogue phase 3: quantize register tile -> d_out (streaming) ----
    float* outq = reinterpret_cast<float*>(d_out);
    const long long qelems = R * (long long)K;
#pragma unroll
    for (int mi = 0; mi < 4; mi++) {
#pragma unroll
        for (int half = 0; half < 2; half++) {
            int r = m0 + wm * 64 + mi * 16 + half * 8 + g;
            unsigned ab;
            asm volatile("ld.global.cg.u32 %0, [%1];"
                         : "=r"(ab) : "l"(&g_absmax[r]));
            const float amax = __uint_as_float(ab);
            const float scale = amax / 127.0f;
            const float inv = (scale == 0.0f) ? 1.0f : (1.0f / scale);
            float* qrow = outq + (size_t)r * K + n0 + wn * 64;
#pragma unroll
            for (int ni = 0; ni < 8; ni++) {
                float q0 = rintf(d[mi][ni][half * 2 + 0] * inv);
                float q1 = rintf(d[mi][ni][half * 2 + 1] * inv);
                q0 = fminf(fmaxf(q0, -127.0f), 127.0f);
                q1 = fminf(fmaxf(q1, -127.0f), 127.0f);
                st_cs_f2(qrow + ni * 8 + tc, q0, q1);
            }
        }
    }
    if (blockIdx.x == 0) {
        int r = m0 + tid;
        unsigned ab;
        asm volatile("ld.global.cg.u32 %0, [%1];"
                     : "=r"(ab) : "l"(&g_absmax[r]));
        outq[qelems + r] = __uint_as_float(ab) / 127.0f;
    }
}

// ============================================================================
// quantize fallback for modes 1/2
// ============================================================================
__global__ void __launch_bounds__(256) quant_kernel(void* __restrict__ d_out,
                                                    int K, long long R, int mode) {
    const int r = blockIdx.x;
    const int tid = threadIdx.x;
    const float amax = __uint_as_float(g_absmax[r]);
    const float scale = amax / 127.0f;
    const float safe = (scale == 0.0f) ? 1.0f : scale;
    const float inv = 1.0f / safe;

    const float4* yrow = reinterpret_cast<const float4*>(g_y + (size_t)r * K);
    const long long qelems = R * (long long)K;

    for (int i = tid; i < K / 4; i += 256) {
        float4 v = yrow[i];
        float vals[4] = {v.x, v.y, v.z, v.w};
        int q[4];
#pragma unroll
        for (int j = 0; j < 4; j++) {
            float t = rintf(vals[j] * inv);
            q[j] = (int)fminf(fmaxf(t, -127.0f), 127.0f);
        }
        uint32_t p = (uint32_t)(q[0] & 0xFF) | ((uint32_t)(q[1] & 0xFF) << 8) |
                     ((uint32_t)(q[2] & 0xFF) << 16) | ((uint32_t)(q[3] & 0xFF) << 24);
        reinterpret_cast<uint32_t*>(
            reinterpret_cast<char*>(d_out) + (size_t)r * K)[i] = p;
    }
    if (tid == 0 && mode == 1) {
        float* sc = reinterpret_cast<float*>(
            reinterpret_cast<char*>(d_out) + qelems);
        sc[r] = scale;
    }
}

// ============================================================================
// launcher (graph-capture clean)
// ============================================================================
static int isqrt_ll(long long v) {
    long long r = (long long)sqrt((double)v);
    while (r * r > v) r--;
    while ((r + 1) * (r + 1) <= v) r++;
    return (int)r;
}

extern "C" void kernel_launch(void* const* d_in, const int* in_sizes, int n_in,
                              void* d_out, int out_size) {
    long long s0 = in_sizes[0], s1 = (n_in > 1) ? in_sizes[1] : 0;
    const void* xv; const void* hv;
    long long numel_x, numel_h;
    if (s0 >= s1) { xv = d_in[0]; numel_x = s0; hv = d_in[1]; numel_h = s1; }
    else          { xv = d_in[1]; numel_x = s1; hv = d_in[0]; numel_h = s0; }
    const int K = isqrt_ll(numel_h);        // 2048
    const long long R = numel_x / K;        // 32768
    const long long qelems = R * (long long)K;

    int mode;
    if ((long long)out_size == qelems + R)            mode = 0;
    else if ((long long)out_size == qelems + 4LL * R) mode = 1;
    else                                              mode = 2;

    cudaFuncSetAttribute(gemm_fused_kernel,
                         cudaFuncAttributeMaxDynamicSharedMemorySize, SMEM_TOTAL);

    const int tb = (K / 32) * (K / 32);               // 4096 transpose blocks
    const unsigned cb = (unsigned)((numel_x / 8 + 255) / 256);
    prep_kernel<<<cb + tb, 256>>>((const float4*)xv, numel_x / 4,
                                  (const float*)hv, K, (int)R, tb);
    gemm_fused_kernel<<<dim3(K / NT, (unsigned)(R / MT)), THREADS, SMEM_TOTAL>>>(
        d_out, K, R, mode);
    if (mode != 0)
        quant_kernel<<<(unsigned)R, 256>>>(d_out, K, R, mode);
}